// round 1
// baseline (speedup 1.0000x reference)
#include <cuda_runtime.h>
#include <cuda_bf16.h>

// Dynamic grouped depthwise 1D conv:
//   x: [B=8, C=512, L=4096] f32
//   w: [B=8, WC=64, KS=7, L=4096] f32, groups = C/WC = 8
//   out[b,c,l] = sum_k x_pad[b,c,l+k] * w[b, c/groups, k, l],  pad = 3 (zeros)
//
// Block = (L-tile of 512, weight-channel wc, batch b). The block stages the
// 7x512 weight tile in shared ONCE and serves all 8 channels of the group
// from it (the only data reuse in the problem). x tiles (with 3-halo) are
// also staged in shared so the sliding window is conflict-free LDS.128.

#define B_DIM 8
#define C_DIM 512
#define L_DIM 4096
#define WC_DIM 64
#define KS 7
#define PAD 3
#define GROUPS 8           // C / WC
#define TILE_L 512
#define THREADS 256
#define XROW (TILE_L + 8)  // 520 floats: 512 + 6 halo + 2 pad (keeps 16B row alignment)

__global__ __launch_bounds__(THREADS, 1)
void SKA_40106404610132_kernel(const float* __restrict__ x,
                               const float* __restrict__ w,
                               float* __restrict__ out)
{
    __shared__ float ws[KS][TILE_L];
    __shared__ float xs[GROUPS][XROW];

    const int tile = blockIdx.x;          // 0..L/TILE_L-1
    const int wc   = blockIdx.y;          // 0..WC-1
    const int b    = blockIdx.z;          // 0..B-1
    const int l0   = tile * TILE_L;
    const int tid  = threadIdx.x;

    // ---- stage weight tile: w[b][wc][k][l0 .. l0+511], float4 loads ----
    const float* wbase = w + (((long)b * WC_DIM + wc) * KS) * L_DIM + l0;
    #pragma unroll 1
    for (int idx = tid; idx < KS * (TILE_L / 4); idx += THREADS) {
        const int k = idx / (TILE_L / 4);
        const int f = idx % (TILE_L / 4);
        reinterpret_cast<float4*>(ws[k])[f] =
            reinterpret_cast<const float4*>(wbase + (long)k * L_DIM)[f];
    }

    // ---- stage x tiles with halo: xs[ch][s] = x[b][c0+ch][l0 + s - PAD] ----
    const int c0 = wc * GROUPS;
    const float* xbase = x + ((long)b * C_DIM + c0) * L_DIM;
    const int NX = TILE_L + 2 * PAD;  // 518
    #pragma unroll 1
    for (int idx = tid; idx < GROUPS * NX; idx += THREADS) {
        const int ch = idx / NX;
        const int s  = idx % NX;
        const int l  = l0 + s - PAD;
        float v = 0.0f;
        if (l >= 0 && l < L_DIM) v = xbase[(long)ch * L_DIM + l];
        xs[ch][s] = v;
    }
    __syncthreads();

    // ---- compute: warp i owns channel c0+i; lanes own float4 outputs ----
    const int warp = tid >> 5;            // 0..7 -> channel within group
    const int lane = tid & 31;
    float* obase = out + ((long)b * C_DIM + c0 + warp) * L_DIM + l0;
    const float4* xs4 = reinterpret_cast<const float4*>(xs[warp]);

    #pragma unroll
    for (int i = 0; i < TILE_L / 4 / 32; i++) {   // 4 iterations
        const int f = lane + i * 32;              // float4 index in tile
        // x window: elements 4f .. 4f+9 (halo-shifted), fetched as 3 float4
        const float4 xa = xs4[f];
        const float4 xb = xs4[f + 1];
        const float4 xc = xs4[f + 2];
        float xv[12];
        xv[0] = xa.x; xv[1]  = xa.y; xv[2]  = xa.z; xv[3]  = xa.w;
        xv[4] = xb.x; xv[5]  = xb.y; xv[6]  = xb.z; xv[7]  = xb.w;
        xv[8] = xc.x; xv[9]  = xc.y; xv[10] = xc.z; xv[11] = xc.w;

        float4 acc = make_float4(0.f, 0.f, 0.f, 0.f);
        #pragma unroll
        for (int k = 0; k < KS; k++) {
            const float4 wv = reinterpret_cast<const float4*>(ws[k])[f];
            acc.x = fmaf(xv[k + 0], wv.x, acc.x);
            acc.y = fmaf(xv[k + 1], wv.y, acc.y);
            acc.z = fmaf(xv[k + 2], wv.z, acc.z);
            acc.w = fmaf(xv[k + 3], wv.w, acc.w);
        }
        reinterpret_cast<float4*>(obase)[f] = acc;
    }
}

extern "C" void kernel_launch(void* const* d_in, const int* in_sizes, int n_in,
                              void* d_out, int out_size) {
    const float* x = (const float*)d_in[0];  // [8, 512, 4096]
    const float* w = (const float*)d_in[1];  // [8, 64, 7, 4096]
    float* out = (float*)d_out;              // [8, 512, 4096]

    dim3 grid(L_DIM / TILE_L, WC_DIM, B_DIM);  // (8, 64, 8) = 4096 blocks
    SKA_40106404610132_kernel<<<grid, THREADS>>>(x, w, out);
}

// round 2
// speedup vs baseline: 2.4613x; 2.4613x over previous
#include <cuda_runtime.h>
#include <cuda_bf16.h>

// Dynamic grouped depthwise 1D conv:
//   x: [B=8, C=512, L=4096] f32
//   w: [B=8, WC=64, KS=7, L=4096] f32, groups = C/WC = 8
//   out[b,c,l] = sum_k x_pad[b,c,l+k] * w[b, c/groups, k, l],  pad = 3 (zeros)
//
// R2: w tile staged in shared (8x reuse across the group's channels); x read
// directly from global (no reuse beyond a 3-elem halo -> L1). Register cap
// via __launch_bounds__(256,5) to get 40 warps/SM (R1 was reg-limited to 24).

#define B_DIM 8
#define C_DIM 512
#define L_DIM 4096
#define WC_DIM 64
#define KS 7
#define GROUPS 8           // C / WC
#define TILE_L 512
#define TILE_F (TILE_L / 4)   // 128 float4 per tile row
#define THREADS 256

__global__ __launch_bounds__(THREADS, 5)
void SKA_40106404610132_kernel(const float* __restrict__ x,
                               const float* __restrict__ w,
                               float* __restrict__ out)
{
    __shared__ float ws[KS][TILE_L];   // 14 KB

    const int tile = blockIdx.x;          // 0..7
    const int wc   = blockIdx.y;          // 0..63
    const int b    = blockIdx.z;          // 0..7
    const int l0   = tile * TILE_L;
    const int tid  = threadIdx.x;

    // ---- stage weight tile: w[b][wc][k][l0 .. l0+511] ----
    const float* wbase = w + (((long)b * WC_DIM + wc) * KS) * L_DIM + l0;
    #pragma unroll 1
    for (int idx = tid; idx < KS * TILE_F; idx += THREADS) {
        const int k = idx >> 7;            // / TILE_F
        const int f = idx & (TILE_F - 1);  // % TILE_F
        reinterpret_cast<float4*>(ws[k])[f] =
            reinterpret_cast<const float4*>(wbase + (long)k * L_DIM)[f];
    }
    __syncthreads();

    // ---- compute: warp i owns channel c0+i; lanes own float4 outputs ----
    const int warp = tid >> 5;             // channel within group
    const int lane = tid & 31;
    const long row = (long)b * C_DIM + wc * GROUPS + warp;
    const float4* x4 = reinterpret_cast<const float4*>(x + row * L_DIM);
    float4* o4 = reinterpret_cast<float4*>(out + row * L_DIM + l0);
    const float4 zero4 = make_float4(0.f, 0.f, 0.f, 0.f);

    #pragma unroll 1
    for (int i = 0; i < TILE_F / 32; i++) {     // 4 iterations
        const int fl = lane + i * 32;           // float4 idx within tile
        const int fg = tile * TILE_F + fl;      // float4 idx within row [0,1024)

        // window x[4fg-3 .. 4fg+6]: 3 float4 loads, edge-predicated
        const float4 xb = x4[fg];
        const float4 xa = (fg > 0)                  ? x4[fg - 1] : zero4;
        const float4 xc = (fg < L_DIM / 4 - 1)      ? x4[fg + 1] : zero4;

        float xv[10];
        xv[0] = xa.y; xv[1] = xa.z; xv[2] = xa.w;
        xv[3] = xb.x; xv[4] = xb.y; xv[5] = xb.z; xv[6] = xb.w;
        xv[7] = xc.x; xv[8] = xc.y; xv[9] = xc.z;

        float4 acc = make_float4(0.f, 0.f, 0.f, 0.f);
        #pragma unroll
        for (int k = 0; k < KS; k++) {
            const float4 wv = reinterpret_cast<const float4*>(ws[k])[fl];
            acc.x = fmaf(xv[k + 0], wv.x, acc.x);
            acc.y = fmaf(xv[k + 1], wv.y, acc.y);
            acc.z = fmaf(xv[k + 2], wv.z, acc.z);
            acc.w = fmaf(xv[k + 3], wv.w, acc.w);
        }
        o4[fl] = acc;
    }
}

extern "C" void kernel_launch(void* const* d_in, const int* in_sizes, int n_in,
                              void* d_out, int out_size) {
    const float* x = (const float*)d_in[0];  // [8, 512, 4096]
    const float* w = (const float*)d_in[1];  // [8, 64, 7, 4096]
    float* out = (float*)d_out;              // [8, 512, 4096]

    dim3 grid(L_DIM / TILE_L, WC_DIM, B_DIM);  // (8, 64, 8) = 4096 blocks
    SKA_40106404610132_kernel<<<grid, THREADS>>>(x, w, out);
}

// round 3
// speedup vs baseline: 3.0731x; 1.2486x over previous
#include <cuda_runtime.h>
#include <cuda_bf16.h>

// Dynamic grouped depthwise 1D conv:
//   x: [B=8, C=512, L=4096] f32
//   w: [B=8, WC=64, KS=7, L=4096] f32, groups = C/WC = 8
//   out[b,c,l] = sum_k x_pad[b,c,l+k] * w[b, c/groups, k, l],  pad = 3 (zeros)
//
// R3: 2 channels per thread -> each shared w read feeds 2 channels' FMAs,
// halving LDS traffic (the L1 crossbar was on track to cap before DRAM).
// 512 thr/block, 1 output float4-position per thread per channel, 6 LDGs
// front-batched for MLP. w tile still staged in shared once per group.

#define B_DIM 8
#define C_DIM 512
#define L_DIM 4096
#define WC_DIM 64
#define KS 7
#define GROUPS 8              // C / WC
#define TILE_L 512
#define TILE_F (TILE_L / 4)   // 128 float4 positions per tile
#define THREADS 512

__global__ __launch_bounds__(THREADS, 2)
void SKA_40106404610132_kernel(const float* __restrict__ x,
                               const float* __restrict__ w,
                               float* __restrict__ out)
{
    __shared__ float ws[KS][TILE_L];   // 14 KB

    const int tile = blockIdx.x;          // 0..7
    const int wc   = blockIdx.y;          // 0..63
    const int b    = blockIdx.z;          // 0..7
    const int l0   = tile * TILE_L;
    const int tid  = threadIdx.x;

    // ---- stage weight tile: w[b][wc][k][l0 .. l0+511] ----
    const float* wbase = w + (((long)b * WC_DIM + wc) * KS) * L_DIM + l0;
    #pragma unroll
    for (int idx = tid; idx < KS * TILE_F; idx += THREADS) {   // 2 iters (896/512)
        const int k = idx >> 7;
        const int f = idx & (TILE_F - 1);
        reinterpret_cast<float4*>(ws[k])[f] =
            reinterpret_cast<const float4*>(wbase + (long)k * L_DIM)[f];
    }
    __syncthreads();

    // ---- thread -> (position f, channel pair cq) ----
    const int f  = tid & (TILE_F - 1);    // 0..127
    const int cq = tid >> 7;              // 0..3 -> channels 2cq, 2cq+1
    const int fg = tile * TILE_F + f;     // float4 idx within row [0,1024)

    const long row0 = (long)b * C_DIM + wc * GROUPS + cq * 2;
    const float4* x0 = reinterpret_cast<const float4*>(x + row0 * L_DIM);
    const float4* x1 = reinterpret_cast<const float4*>(x + (row0 + 1) * L_DIM);

    const float4 zero4 = make_float4(0.f, 0.f, 0.f, 0.f);
    const bool has_lo = (fg > 0);
    const bool has_hi = (fg < L_DIM / 4 - 1);

    // 6 front-batched LDG.128: window x[4fg-3 .. 4fg+6] per channel
    const float4 xb0 = x0[fg];
    const float4 xb1 = x1[fg];
    const float4 xa0 = has_lo ? x0[fg - 1] : zero4;
    const float4 xa1 = has_lo ? x1[fg - 1] : zero4;
    const float4 xc0 = has_hi ? x0[fg + 1] : zero4;
    const float4 xc1 = has_hi ? x1[fg + 1] : zero4;

    float u[10], v[10];
    u[0] = xa0.y; u[1] = xa0.z; u[2] = xa0.w;
    u[3] = xb0.x; u[4] = xb0.y; u[5] = xb0.z; u[6] = xb0.w;
    u[7] = xc0.x; u[8] = xc0.y; u[9] = xc0.z;
    v[0] = xa1.y; v[1] = xa1.z; v[2] = xa1.w;
    v[3] = xb1.x; v[4] = xb1.y; v[5] = xb1.z; v[6] = xb1.w;
    v[7] = xc1.x; v[8] = xc1.y; v[9] = xc1.z;

    float4 acc0 = zero4, acc1 = zero4;
    #pragma unroll
    for (int k = 0; k < KS; k++) {
        const float4 wv = reinterpret_cast<const float4*>(ws[k])[f];
        acc0.x = fmaf(u[k + 0], wv.x, acc0.x);
        acc0.y = fmaf(u[k + 1], wv.y, acc0.y);
        acc0.z = fmaf(u[k + 2], wv.z, acc0.z);
        acc0.w = fmaf(u[k + 3], wv.w, acc0.w);
        acc1.x = fmaf(v[k + 0], wv.x, acc1.x);
        acc1.y = fmaf(v[k + 1], wv.y, acc1.y);
        acc1.z = fmaf(v[k + 2], wv.z, acc1.z);
        acc1.w = fmaf(v[k + 3], wv.w, acc1.w);
    }

    float4* o0 = reinterpret_cast<float4*>(out + row0 * L_DIM + l0);
    float4* o1 = reinterpret_cast<float4*>(out + (row0 + 1) * L_DIM + l0);
    o0[f] = acc0;
    o1[f] = acc1;
}

extern "C" void kernel_launch(void* const* d_in, const int* in_sizes, int n_in,
                              void* d_out, int out_size) {
    const float* x = (const float*)d_in[0];  // [8, 512, 4096]
    const float* w = (const float*)d_in[1];  // [8, 64, 7, 4096]
    float* out = (float*)d_out;              // [8, 512, 4096]

    dim3 grid(L_DIM / TILE_L, WC_DIM, B_DIM);  // (8, 64, 8) = 4096 blocks
    SKA_40106404610132_kernel<<<grid, THREADS>>>(x, w, out);
}